// round 7
// baseline (speedup 1.0000x reference)
#include <cuda_runtime.h>
#include <cuda_bf16.h>
#include <cstdint>

#define MAX_NODES 100000
#define MAX_EDGES 1600000
#define D 64
#define D4 (D / 4)

// ---------------------------------------------------------------------------
// Scratch (allocation-free rule -> device globals). All int; no float atomics.
// ---------------------------------------------------------------------------
__device__ int g_deg[MAX_NODES];
__device__ int g_off[MAX_NODES];
__device__ int g_cursor[MAX_NODES];
__device__ int g_bsum[1024];
__device__ int g_elist[MAX_EDGES];

// ---------------------------------------------------------------------------
// K1: zero degree counters
// ---------------------------------------------------------------------------
__global__ void zero_deg(int n) {
    int i = blockIdx.x * blockDim.x + threadIdx.x;
    if (i < n) g_deg[i] = 0;
}

// ---------------------------------------------------------------------------
// K2: count in-degree per dst  (src/dst are INT32 — JAX x64-disabled downcast)
// ---------------------------------------------------------------------------
__global__ void count_deg(const int* __restrict__ dst, int e) {
    int i = blockIdx.x * blockDim.x + threadIdx.x;
    if (i < e) atomicAdd(&g_deg[dst[i]], 1);
}

// ---------------------------------------------------------------------------
// K3a/b/c: exclusive scan of g_deg -> g_off  (1024 items per block)
// ---------------------------------------------------------------------------
__global__ __launch_bounds__(1024) void scan_blocks(int n) {
    __shared__ int s[1024];
    int tid = threadIdx.x;
    int i = blockIdx.x * 1024 + tid;
    int v = (i < n) ? g_deg[i] : 0;
    s[tid] = v;
    __syncthreads();
#pragma unroll
    for (int ofs = 1; ofs < 1024; ofs <<= 1) {
        int t = (tid >= ofs) ? s[tid - ofs] : 0;
        __syncthreads();
        s[tid] += t;
        __syncthreads();
    }
    if (i < n) g_off[i] = s[tid] - v;            // exclusive
    if (tid == 1023) g_bsum[blockIdx.x] = s[1023];
}

__global__ __launch_bounds__(1024) void scan_bsums(int nb) {
    __shared__ int s[1024];
    int tid = threadIdx.x;
    int v = (tid < nb) ? g_bsum[tid] : 0;
    s[tid] = v;
    __syncthreads();
#pragma unroll
    for (int ofs = 1; ofs < 1024; ofs <<= 1) {
        int t = (tid >= ofs) ? s[tid - ofs] : 0;
        __syncthreads();
        s[tid] += t;
        __syncthreads();
    }
    if (tid < nb) g_bsum[tid] = s[tid] - v;      // exclusive block offsets
}

__global__ void scan_add(int n) {
    int i = blockIdx.x * blockDim.x + threadIdx.x;
    if (i < n) {
        int o = g_off[i] + g_bsum[i >> 10];
        g_off[i] = o;
        g_cursor[i] = o;
    }
}

// ---------------------------------------------------------------------------
// K4: fill per-dst edge lists (src ids, grouped by dst)
// ---------------------------------------------------------------------------
__global__ void fill_elist(const int* __restrict__ src,
                           const int* __restrict__ dst, int e) {
    int i = blockIdx.x * blockDim.x + threadIdx.x;
    if (i < e) {
        int d = dst[i];
        int pos = atomicAdd(&g_cursor[d], 1);
        g_elist[pos] = src[i];
    }
}

// ---------------------------------------------------------------------------
// K5: fused pull-aggregate + normalize + dual GEMM + bias + ReLU.
// Block = 256 threads, 16 nodes per block.
// Phase A: 16 threads per node gather+sum neighbor feat rows (float4/thread),
//          unrolled x4 for MLP; pure LDGs, no atomics.
// Phase B: j = tid&63 output column; each thread owns 4 nodes' accumulators;
//          weights loaded to registers once per k-chunk (reused across nodes)
//          -> FMA-bound, not LDS-bound.
// ---------------------------------------------------------------------------
__global__ __launch_bounds__(256)
void sage_pull(const float4* __restrict__ feat4,
               const float* __restrict__ W_self,
               const float* __restrict__ W_neigh,
               const float* __restrict__ bias,
               float* __restrict__ out,
               int n) {
    __shared__ float sWs[D][D];      // 16 KB
    __shared__ float sWn[D][D];      // 16 KB
    __shared__ float4 sf4[16][D4];   // 4 KB  self rows
    __shared__ float4 sh4[16][D4];   // 4 KB  normalized neighbor rows

    int tid = threadIdx.x;

    // stage weights
    for (int i = tid; i < D * D; i += 256) {
        sWs[i >> 6][i & 63] = W_self[i];
        sWn[i >> 6][i & 63] = W_neigh[i];
    }

    // ---------- Phase A: gather ----------
    int nodeLocal = tid >> 4;        // 0..15
    int lane16    = tid & 15;        // float4 chunk within row
    int node      = blockIdx.x * 16 + nodeLocal;

    if (node < n) {
        int start = g_off[node];
        int g     = g_deg[node];
        float4 acc = make_float4(0.f, 0.f, 0.f, 0.f);
        int k = 0;
        for (; k + 4 <= g; k += 4) {            // unroll 4 for MLP
            int s0 = g_elist[start + k + 0];
            int s1 = g_elist[start + k + 1];
            int s2 = g_elist[start + k + 2];
            int s3 = g_elist[start + k + 3];
            float4 v0 = feat4[(size_t)s0 * D4 + lane16];
            float4 v1 = feat4[(size_t)s1 * D4 + lane16];
            float4 v2 = feat4[(size_t)s2 * D4 + lane16];
            float4 v3 = feat4[(size_t)s3 * D4 + lane16];
            acc.x += v0.x + v1.x + v2.x + v3.x;
            acc.y += v0.y + v1.y + v2.y + v3.y;
            acc.z += v0.z + v1.z + v2.z + v3.z;
            acc.w += v0.w + v1.w + v2.w + v3.w;
        }
        for (; k < g; k++) {
            int s0 = g_elist[start + k];
            float4 v0 = feat4[(size_t)s0 * D4 + lane16];
            acc.x += v0.x; acc.y += v0.y; acc.z += v0.z; acc.w += v0.w;
        }
        float inv = 1.0f / (float)max(g, 1);
        acc.x *= inv; acc.y *= inv; acc.z *= inv; acc.w *= inv;
        sh4[nodeLocal][lane16] = acc;
        sf4[nodeLocal][lane16] = feat4[(size_t)node * D4 + lane16];
    }
    __syncthreads();

    // ---------- Phase B: GEMM ----------
    int j   = tid & 63;              // output column
    int sub = tid >> 6;              // 0..3 -> nodes sub, sub+4, sub+8, sub+12

    const float* sf = reinterpret_cast<const float*>(sf4);  // [16][64]
    const float* sh = reinterpret_cast<const float*>(sh4);

    float b = bias[j];
    float a0 = b, a1 = b, a2 = b, a3 = b;

#pragma unroll
    for (int kc = 0; kc < D; kc += 4) {
        // weights -> registers once, reused across 4 nodes
        float ws0 = sWs[kc + 0][j], ws1 = sWs[kc + 1][j];
        float ws2 = sWs[kc + 2][j], ws3 = sWs[kc + 3][j];
        float wn0 = sWn[kc + 0][j], wn1 = sWn[kc + 1][j];
        float wn2 = sWn[kc + 2][j], wn3 = sWn[kc + 3][j];

        const float4 f0 = *reinterpret_cast<const float4*>(&sf[(sub + 0) * D + kc]);
        const float4 h0 = *reinterpret_cast<const float4*>(&sh[(sub + 0) * D + kc]);
        const float4 f1 = *reinterpret_cast<const float4*>(&sf[(sub + 4) * D + kc]);
        const float4 h1 = *reinterpret_cast<const float4*>(&sh[(sub + 4) * D + kc]);
        const float4 f2 = *reinterpret_cast<const float4*>(&sf[(sub + 8) * D + kc]);
        const float4 h2 = *reinterpret_cast<const float4*>(&sh[(sub + 8) * D + kc]);
        const float4 f3 = *reinterpret_cast<const float4*>(&sf[(sub + 12) * D + kc]);
        const float4 h3 = *reinterpret_cast<const float4*>(&sh[(sub + 12) * D + kc]);

        a0 = fmaf(f0.x, ws0, fmaf(f0.y, ws1, fmaf(f0.z, ws2, fmaf(f0.w, ws3, a0))));
        a0 = fmaf(h0.x, wn0, fmaf(h0.y, wn1, fmaf(h0.z, wn2, fmaf(h0.w, wn3, a0))));
        a1 = fmaf(f1.x, ws0, fmaf(f1.y, ws1, fmaf(f1.z, ws2, fmaf(f1.w, ws3, a1))));
        a1 = fmaf(h1.x, wn0, fmaf(h1.y, wn1, fmaf(h1.z, wn2, fmaf(h1.w, wn3, a1))));
        a2 = fmaf(f2.x, ws0, fmaf(f2.y, ws1, fmaf(f2.z, ws2, fmaf(f2.w, ws3, a2))));
        a2 = fmaf(h2.x, wn0, fmaf(h2.y, wn1, fmaf(h2.z, wn2, fmaf(h2.w, wn3, a2))));
        a3 = fmaf(f3.x, ws0, fmaf(f3.y, ws1, fmaf(f3.z, ws2, fmaf(f3.w, ws3, a3))));
        a3 = fmaf(h3.x, wn0, fmaf(h3.y, wn1, fmaf(h3.z, wn2, fmaf(h3.w, wn3, a3))));
    }

    int base = blockIdx.x * 16;
    int n0 = base + sub, n1 = base + sub + 4, n2 = base + sub + 8, n3 = base + sub + 12;
    if (n0 < n) out[(size_t)n0 * D + j] = fmaxf(a0, 0.f);
    if (n1 < n) out[(size_t)n1 * D + j] = fmaxf(a1, 0.f);
    if (n2 < n) out[(size_t)n2 * D + j] = fmaxf(a2, 0.f);
    if (n3 < n) out[(size_t)n3 * D + j] = fmaxf(a3, 0.f);
}

// ---------------------------------------------------------------------------
// Launch.  Inputs: feat[N*64] f32, src[E] i32, dst[E] i32,
//                  W_self[64*64] f32, W_neigh[64*64] f32, bias[64] f32
// ---------------------------------------------------------------------------
extern "C" void kernel_launch(void* const* d_in, const int* in_sizes, int n_in,
                              void* d_out, int out_size) {
    const float* feat    = (const float*)d_in[0];
    const int*   src     = (const int*)d_in[1];
    const int*   dst     = (const int*)d_in[2];
    const float* W_self  = (const float*)d_in[3];
    const float* W_neigh = (const float*)d_in[4];
    const float* bias    = (const float*)d_in[5];
    float*       out     = (float*)d_out;

    int n = in_sizes[0] / D;
    int e = in_sizes[1];

    int nb256  = (n + 255) / 256;
    int eb256  = (e + 255) / 256;
    int nScanB = (n + 1023) / 1024;

    zero_deg<<<nb256, 256>>>(n);
    count_deg<<<eb256, 256>>>(dst, e);
    scan_blocks<<<nScanB, 1024>>>(n);
    scan_bsums<<<1, 1024>>>(nScanB);
    scan_add<<<nb256, 256>>>(n);
    fill_elist<<<eb256, 256>>>(src, dst, e);
    sage_pull<<<(n + 15) / 16, 256>>>(reinterpret_cast<const float4*>(feat),
                                      W_self, W_neigh, bias, out, n);
}